// round 2
// baseline (speedup 1.0000x reference)
#include <cuda_runtime.h>
#include <cuda_bf16.h>
#include <cstdio>

// ---------------------------------------------------------------------------
// HybridAttention — round 1: correct fp32 pipeline, tiled SGEMM for 1x1 convs.
// B=4, C=192, H=W=256, HEADS=8, WS=8, ch=24, HW=65536, down 32x32 (1024 px)
// ---------------------------------------------------------------------------

#define DIMC   192
#define HEADS  8
#define CH     24          // DIMC/HEADS
#define HH     256
#define WW     256
#define HW     65536       // 256*256
#define HD     32
#define WD     32
#define PD     1024        // 32*32
#define BATCH  4

// ------------------------- scratch (static device) -------------------------
__device__ float g_hcatdw[(size_t)BATCH * 384 * HW];   // fused strip+3x3 dw out
__device__ float g_cat   [(size_t)BATCH * 384 * HW];   // [high(0:192) | low(192:384)]
__device__ float g_t4    [(size_t)BATCH * DIMC * HW];  // conv4a out
__device__ float g_vfull [(size_t)BATCH * DIMC * HW];  // gate * conv4b(t4)
__device__ float g_xdown [(size_t)BATCH * DIMC * PD];
__device__ float g_qkv   [(size_t)BATCH * 576 * PD];
__device__ float g_qkvdw [(size_t)BATCH * 576 * PD];
__device__ float g_attn  [(size_t)BATCH * HEADS * CH * CH];
__device__ float g_gate  [(size_t)BATCH * DIMC];

// ------------------------------ SGEMM ---------------------------------------
// Out[b][m][n] = sum_k W[m][k] * In[b][k][n]
// W: row-major [M,K]; In rows contiguous (stride N); Out rows contiguous.
#define BM 64
#define BN 128
#define BKK 16
#define TM 4
#define TN 8

__global__ __launch_bounds__(256) void gemm_kernel(
    const float* __restrict__ Wt, const float* __restrict__ In,
    float* __restrict__ Out, int K, int N, size_t inBS, size_t outBS)
{
    const int b  = blockIdx.z;
    const float* Ib = In + (size_t)b * inBS;
    float*       Ob = Out + (size_t)b * outBS;
    const int m0 = blockIdx.y * BM;
    const int n0 = blockIdx.x * BN;

    __shared__ float Ws[BKK][BM];
    __shared__ float Is[BKK][BN];

    const int tid = threadIdx.x;
    const int tx = tid & 15;          // 0..15 -> N
    const int ty = tid >> 4;          // 0..15 -> M

    float acc[TM][TN] = {};

    for (int k0 = 0; k0 < K; k0 += BKK) {
        // W tile: 64x16 = 1024 elements
        #pragma unroll
        for (int i = 0; i < 4; i++) {
            int e = tid + i * 256;
            int m = e >> 4, k = e & 15;
            Ws[k][m] = Wt[(size_t)(m0 + m) * K + k0 + k];
        }
        // In tile: 16x128 via float4 (512 vec loads / 256 thr = 2 each)
        #pragma unroll
        for (int i = 0; i < 2; i++) {
            int e = tid + i * 256;          // 0..511
            int k = e >> 5, n4 = e & 31;    // 32 float4 per row
            float4 v = *reinterpret_cast<const float4*>(
                &Ib[(size_t)(k0 + k) * N + n0 + n4 * 4]);
            *reinterpret_cast<float4*>(&Is[k][n4 * 4]) = v;
        }
        __syncthreads();

        #pragma unroll
        for (int k = 0; k < BKK; k++) {
            float4 av = *reinterpret_cast<const float4*>(&Ws[k][ty * TM]);
            float4 b0 = *reinterpret_cast<const float4*>(&Is[k][tx * TN]);
            float4 b1 = *reinterpret_cast<const float4*>(&Is[k][tx * TN + 4]);
            float a[TM] = {av.x, av.y, av.z, av.w};
            float bb[TN] = {b0.x, b0.y, b0.z, b0.w, b1.x, b1.y, b1.z, b1.w};
            #pragma unroll
            for (int i = 0; i < TM; i++)
                #pragma unroll
                for (int j = 0; j < TN; j++)
                    acc[i][j] = fmaf(a[i], bb[j], acc[i][j]);
        }
        __syncthreads();
    }

    #pragma unroll
    for (int i = 0; i < TM; i++) {
        size_t row = (size_t)(m0 + ty * TM + i) * N + n0 + tx * TN;
        *reinterpret_cast<float4*>(&Ob[row]) =
            make_float4(acc[i][0], acc[i][1], acc[i][2], acc[i][3]);
        *reinterpret_cast<float4*>(&Ob[row + 4]) =
            make_float4(acc[i][4], acc[i][5], acc[i][6], acc[i][7]);
    }
}

// --------------------- fused strip conv + 3x3 depthwise ---------------------
// out channel cp<192: 3x3dw( 1x11 horiz dww(x[cp]) ); cp>=192: 3x3dw( 11x1 vert dwh )
__global__ __launch_bounds__(256) void highpre_kernel(
    const float* __restrict__ x,
    const float* __restrict__ w_dww, const float* __restrict__ b_dww,
    const float* __restrict__ w_dwh, const float* __restrict__ b_dwh,
    const float* __restrict__ w_dwhw, const float* __restrict__ b_dwhw)
{
    const int zc = blockIdx.z;
    const int b = zc / 384, cp = zc % 384;
    const bool horiz = (cp < DIMC);
    const int c = horiz ? cp : cp - DIMC;
    const int y0 = blockIdx.y * 32, x0 = blockIdx.x * 32;
    const float* xp = x + ((size_t)b * DIMC + c) * HW;

    __shared__ float xs[44][44];
    __shared__ float ss[34][36];
    __shared__ float wk[11], w3[9];

    const int tid = threadIdx.x;
    if (tid < 11) wk[tid] = horiz ? w_dww[c * 11 + tid] : w_dwh[c * 11 + tid];
    if (tid < 9)  w3[tid] = w_dwhw[cp * 9 + tid];

    for (int i = tid; i < 44 * 44; i += 256) {
        int r = i / 44, cc = i % 44;
        int gy = y0 - 6 + r, gx = x0 - 6 + cc;
        float v = 0.f;
        if (gy >= 0 && gy < HH && gx >= 0 && gx < WW) v = xp[gy * WW + gx];
        xs[r][cc] = v;
    }
    __syncthreads();

    const float bs = horiz ? b_dww[c] : b_dwh[c];
    for (int i = tid; i < 34 * 34; i += 256) {
        int r = i / 34, cc = i % 34;
        int gy = y0 - 1 + r, gx = x0 - 1 + cc;
        float v = 0.f;
        if (gy >= 0 && gy < HH && gx >= 0 && gx < WW) {
            float s = bs;
            if (horiz) {
                #pragma unroll
                for (int k = 0; k < 11; k++) s = fmaf(xs[r + 5][cc + k], wk[k], s);
            } else {
                #pragma unroll
                for (int k = 0; k < 11; k++) s = fmaf(xs[r + k][cc + 5], wk[k], s);
            }
            v = s;
        }
        ss[r][cc] = v;
    }
    __syncthreads();

    const float b3 = b_dwhw[cp];
    float* op = g_hcatdw + ((size_t)b * 384 + cp) * HW;
    const int tx = tid & 31, tyy = tid >> 5;
    #pragma unroll
    for (int rr = 0; rr < 4; rr++) {
        int oy = tyy + rr * 8;
        float s = b3;
        #pragma unroll
        for (int ky = 0; ky < 3; ky++)
            #pragma unroll
            for (int kx = 0; kx < 3; kx++)
                s = fmaf(ss[oy + ky][tx + kx], w3[ky * 3 + kx], s);
        op[(y0 + oy) * WW + x0 + tx] = s;
    }
}

// ----------------------------- avg pool 8x8 ---------------------------------
__global__ void pool_kernel(const float* __restrict__ x)
{
    int idx = blockIdx.x * 256 + threadIdx.x;
    if (idx >= BATCH * DIMC * PD) return;
    int p = idx % PD; int bc = idx / PD;
    int yd = p / WD, xd = p % WD;
    const float* xp = x + (size_t)bc * HW;
    float s = 0.f;
    #pragma unroll
    for (int i = 0; i < 8; i++)
        #pragma unroll
        for (int j = 0; j < 8; j++)
            s += xp[(yd * 8 + i) * WW + xd * 8 + j];
    g_xdown[idx] = s * (1.f / 64.f);
}

// ------------------------- 3x3 depthwise (32x32) ----------------------------
__global__ __launch_bounds__(256) void dw3x3_small_kernel(const float* __restrict__ w)
{
    const int zc = blockIdx.x;                 // b*576 + c
    const int c = zc % 576;
    __shared__ float xs[34][34];
    __shared__ float w3[9];
    const int tid = threadIdx.x;
    const float* ip = g_qkv + (size_t)zc * PD;
    if (tid < 9) w3[tid] = w[c * 9 + tid];
    for (int i = tid; i < 34 * 34; i += 256) {
        int r = i / 34, cc = i % 34;
        int gy = r - 1, gx = cc - 1;
        xs[r][cc] = (gy >= 0 && gy < HD && gx >= 0 && gx < WD) ? ip[gy * WD + gx] : 0.f;
    }
    __syncthreads();
    const int tx = tid & 31, ty = tid >> 5;
    float* op = g_qkvdw + (size_t)zc * PD;
    #pragma unroll
    for (int rr = 0; rr < 4; rr++) {
        int oy = ty + rr * 8;
        float s = 0.f;
        #pragma unroll
        for (int ky = 0; ky < 3; ky++)
            #pragma unroll
            for (int kx = 0; kx < 3; kx++)
                s = fmaf(xs[oy + ky][tx + kx], w3[ky * 3 + kx], s);
        op[oy * WD + tx] = s;
    }
}

// ------------------- 3x3 depthwise (256x256) * gate -------------------------
__global__ __launch_bounds__(256) void dw3x3_gate_kernel(const float* __restrict__ w)
{
    const int zc = blockIdx.z;                 // b*192 + c
    const int b = zc / DIMC, c = zc % DIMC;
    const int y0 = blockIdx.y * 32, x0 = blockIdx.x * 32;
    const float* ip = g_t4 + (size_t)zc * HW;
    __shared__ float xs[34][34];
    __shared__ float w3[9];
    const int tid = threadIdx.x;
    if (tid < 9) w3[tid] = w[c * 9 + tid];
    for (int i = tid; i < 34 * 34; i += 256) {
        int r = i / 34, cc = i % 34;
        int gy = y0 - 1 + r, gx = x0 - 1 + cc;
        xs[r][cc] = (gy >= 0 && gy < HH && gx >= 0 && gx < WW) ? ip[gy * WW + gx] : 0.f;
    }
    __syncthreads();
    const float g = g_gate[b * DIMC + c];
    float* op = g_vfull + (size_t)zc * HW;
    const int tx = tid & 31, ty = tid >> 5;
    #pragma unroll
    for (int rr = 0; rr < 4; rr++) {
        int oy = ty + rr * 8;
        float s = 0.f;
        #pragma unroll
        for (int ky = 0; ky < 3; ky++)
            #pragma unroll
            for (int kx = 0; kx < 3; kx++)
                s = fmaf(xs[oy + ky][tx + kx], w3[ky * 3 + kx], s);
        op[(y0 + oy) * WW + x0 + tx] = g * s;
    }
}

// --------------------- attention Gram + softmax (per b,h) -------------------
__global__ void attn_kernel(const float* __restrict__ temp)
{
    const int bh = blockIdx.x;
    const int h = bh % HEADS;
    const float* base = g_qkvdw + (size_t)(bh / HEADS) * 576 * PD;
    const float* q = base + (size_t)(h * CH) * PD;
    const float* kk = base + (size_t)(DIMC + h * CH) * PD;

    __shared__ float qn[CH], kn[CH], sm[CH][CH];
    const int tid = threadIdx.x;    // 576

    if (tid < 48) {
        const float* p = (tid < CH) ? q + (size_t)tid * PD : kk + (size_t)(tid - CH) * PD;
        float s = 0.f;
        for (int n = 0; n < PD; n++) { float v = p[n]; s = fmaf(v, v, s); }
        float nv = fmaxf(sqrtf(s), 1e-12f);
        if (tid < CH) qn[tid] = nv; else kn[tid - CH] = nv;
    }
    __syncthreads();
    {
        int c = tid / CH, d = tid % CH;
        const float* qa = q + (size_t)c * PD;
        const float* ka = kk + (size_t)d * PD;
        float s = 0.f;
        for (int n = 0; n < PD; n++) s = fmaf(qa[n], ka[n], s);
        sm[c][d] = s / (qn[c] * kn[d]) * temp[h];
    }
    __syncthreads();
    if (tid < CH) {
        int c = tid;
        float m = -1e30f;
        for (int d = 0; d < CH; d++) m = fmaxf(m, sm[c][d]);
        float e[CH]; float ssum = 0.f;
        for (int d = 0; d < CH; d++) { e[d] = expf(sm[c][d] - m); ssum += e[d]; }
        float inv = 1.f / ssum;
        for (int d = 0; d < CH; d++)
            g_attn[((size_t)bh * CH + c) * CH + d] = e[d] * inv;
    }
}

// ------------------------------ v gate --------------------------------------
__global__ void vgate_kernel(const float* __restrict__ w2, const float* __restrict__ w3)
{
    const int b = blockIdx.x;
    const float* v = g_qkvdw + ((size_t)b * 576 + 2 * DIMC) * PD;
    __shared__ float vmax[DIMC], vavg[DIMC];
    const int tid = threadIdx.x;   // 192
    {
        const float* p = v + (size_t)tid * PD;
        float m = -1e30f, s = 0.f;
        for (int n = 0; n < PD; n++) { float vv = p[n]; m = fmaxf(m, vv); s += vv; }
        vmax[tid] = m; vavg[tid] = s * (1.f / (float)PD);
    }
    __syncthreads();
    float g = 0.f;
    for (int c = 0; c < DIMC; c++)
        g = fmaf(w2[tid * DIMC + c], vmax[c], fmaf(w3[tid * DIMC + c], vavg[c], g));
    g_gate[b * DIMC + tid] = g;
}

// ------------------------- attention apply (low) ----------------------------
__global__ __launch_bounds__(256) void attnapply_kernel()
{
    const int b = blockIdx.z, h = blockIdx.y;
    const int p = blockIdx.x * 256 + threadIdx.x;
    __shared__ float a[CH][CH];
    const int tid = threadIdx.x;
    for (int i = tid; i < CH * CH; i += 256)
        a[i / CH][i % CH] = g_attn[(size_t)(b * HEADS + h) * CH * CH + i];
    __syncthreads();

    const float* vb = g_vfull + ((size_t)b * DIMC + h * CH) * HW + p;
    float v[CH];
    #pragma unroll
    for (int d = 0; d < CH; d++) v[d] = vb[(size_t)d * HW];
    float* ob = g_cat + ((size_t)b * 384 + DIMC + h * CH) * HW + p;
    #pragma unroll
    for (int c = 0; c < CH; c++) {
        float s = 0.f;
        #pragma unroll
        for (int d = 0; d < CH; d++) s = fmaf(a[c][d], v[d], s);
        ob[(size_t)c * HW] = s;
    }
}

// ------------------------------- launch -------------------------------------
extern "C" void kernel_launch(void* const* d_in, const int* in_sizes, int n_in,
                              void* d_out, int out_size)
{
    const float* x        = (const float*)d_in[0];
    const float* w_dww    = (const float*)d_in[1];
    const float* b_dww    = (const float*)d_in[2];
    const float* w_dwh    = (const float*)d_in[3];
    const float* b_dwh    = (const float*)d_in[4];
    const float* w_dwhw   = (const float*)d_in[5];
    const float* b_dwhw   = (const float*)d_in[6];
    const float* w_conv1  = (const float*)d_in[7];
    const float* w_qkv    = (const float*)d_in[8];
    const float* w_qkvdw  = (const float*)d_in[9];
    const float* w_conv2  = (const float*)d_in[10];
    const float* w_conv3  = (const float*)d_in[11];
    const float* w_conv4a = (const float*)d_in[12];
    const float* w_conv4b = (const float*)d_in[13];
    const float* w_proj   = (const float*)d_in[14];
    const float* temp     = (const float*)d_in[15];
    float* out = (float*)d_out;

    float *p_hcatdw, *p_cat, *p_t4, *p_vfull, *p_xdown, *p_qkv;
    cudaGetSymbolAddress((void**)&p_hcatdw, g_hcatdw);
    cudaGetSymbolAddress((void**)&p_cat,    g_cat);
    cudaGetSymbolAddress((void**)&p_t4,     g_t4);
    cudaGetSymbolAddress((void**)&p_vfull,  g_vfull);
    cudaGetSymbolAddress((void**)&p_xdown,  g_xdown);
    cudaGetSymbolAddress((void**)&p_qkv,    g_qkv);

    // ---- low branch (small) ----
    pool_kernel<<<(BATCH * DIMC * PD + 255) / 256, 256>>>(x);
    // qkv = w_qkv @ x_down : M=576 K=192 N=1024
    gemm_kernel<<<dim3(PD / BN, 576 / BM, BATCH), 256>>>(
        w_qkv, p_xdown, p_qkv, DIMC, PD, (size_t)DIMC * PD, (size_t)576 * PD);
    dw3x3_small_kernel<<<BATCH * 576, 256>>>(w_qkvdw);
    attn_kernel<<<BATCH * HEADS, 576>>>(temp);
    vgate_kernel<<<BATCH, DIMC>>>(w_conv2, w_conv3);

    // ---- high branch ----
    highpre_kernel<<<dim3(WW / 32, HH / 32, BATCH * 384), 256>>>(
        x, w_dww, b_dww, w_dwh, b_dwh, w_dwhw, b_dwhw);
    // conv1: M=192 K=384 N=65536, write into cat channels [0,192)
    gemm_kernel<<<dim3(HW / BN, DIMC / BM, BATCH), 256>>>(
        w_conv1, p_hcatdw, p_cat, 384, HW, (size_t)384 * HW, (size_t)384 * HW);

    // ---- v_full path ----
    gemm_kernel<<<dim3(HW / BN, DIMC / BM, BATCH), 256>>>(
        w_conv4a, x, p_t4, DIMC, HW, (size_t)DIMC * HW, (size_t)DIMC * HW);
    dw3x3_gate_kernel<<<dim3(WW / 32, HH / 32, BATCH * DIMC), 256>>>(w_conv4b);
    attnapply_kernel<<<dim3(HW / 256, HEADS, BATCH), 256>>>();

    // ---- proj: M=192 K=384 N=65536 ----
    gemm_kernel<<<dim3(HW / BN, DIMC / BM, BATCH), 256>>>(
        w_proj, p_cat, out, 384, HW, (size_t)384 * HW, (size_t)DIMC * HW);
}

// round 4
// speedup vs baseline: 2.1726x; 2.1726x over previous
#include <cuda_runtime.h>
#include <cuda_bf16.h>
#include <cstdint>

// ---------------------------------------------------------------------------
// HybridAttention — round 3: mma.sync (HMMA) bf16 hi/lo GEMMs (compute_103-safe)
// B=4, C=192, H=W=256, HEADS=8, WS=8, ch=24, HW=65536, down 32x32 (1024 px)
// ---------------------------------------------------------------------------

#define DIMC   192
#define HEADS  8
#define CH     24
#define HH     256
#define WW     256
#define HW     65536
#define HD     32
#define WD     32
#define PD     1024
#define BATCH  4

// ------------------------- scratch (static device) -------------------------
__device__ float g_hcatdw[(size_t)BATCH * 384 * HW];
__device__ float g_t4    [(size_t)BATCH * DIMC * HW];
__device__ float g_vfull [(size_t)BATCH * DIMC * HW];
__device__ float g_xdown [(size_t)BATCH * DIMC * PD];
__device__ float g_qkv   [(size_t)BATCH * 576 * PD];
__device__ float g_qkvdw [(size_t)BATCH * 576 * PD];
__device__ float g_attn  [(size_t)BATCH * HEADS * CH * CH];
__device__ float g_gate  [(size_t)BATCH * DIMC];

// bf16 hi/lo split activations (pixel-major: [b][px][C])
__device__ __nv_bfloat16 g_hc_hi[(size_t)BATCH * HW * 384];
__device__ __nv_bfloat16 g_hc_lo[(size_t)BATCH * HW * 384];
__device__ __nv_bfloat16 g_x_hi [(size_t)BATCH * HW * DIMC];
__device__ __nv_bfloat16 g_x_lo [(size_t)BATCH * HW * DIMC];
__device__ __nv_bfloat16 g_cat_hi[(size_t)BATCH * HW * 384];
__device__ __nv_bfloat16 g_cat_lo[(size_t)BATCH * HW * 384];
// weights hi/lo (row-major [outch][K])
__device__ __nv_bfloat16 g_w1h[192 * 384], g_w1l[192 * 384];
__device__ __nv_bfloat16 g_w4h[192 * 192], g_w4l[192 * 192];
__device__ __nv_bfloat16 g_wph[192 * 384], g_wpl[192 * 384];

// --------------------------- ptx helpers (sm_80 ISA) ------------------------
__device__ __forceinline__ uint32_t smem_u32(const void* p) {
    uint32_t a;
    asm("{ .reg .u64 t; cvta.to.shared.u64 t, %1; cvt.u32.u64 %0, t; }"
        : "=r"(a) : "l"(p));
    return a;
}
__device__ __forceinline__ void cpasync16(uint32_t saddr, const void* gaddr) {
    asm volatile("cp.async.cg.shared.global [%0], [%1], 16;"
                 :: "r"(saddr), "l"(gaddr));
}
__device__ __forceinline__ void cpcommit() {
    asm volatile("cp.async.commit_group;" ::: "memory");
}
template<int N> __device__ __forceinline__ void cpwait() {
    asm volatile("cp.async.wait_group %0;" :: "n"(N) : "memory");
}
__device__ __forceinline__ void ldsm4(uint32_t* r, uint32_t addr) {
    asm volatile("ldmatrix.sync.aligned.m8n8.x4.shared.b16 {%0,%1,%2,%3}, [%4];"
        : "=r"(r[0]), "=r"(r[1]), "=r"(r[2]), "=r"(r[3]) : "r"(addr));
}
__device__ __forceinline__ void mma16816(float* d, const uint32_t* a,
                                         uint32_t b0, uint32_t b1) {
    asm volatile(
        "mma.sync.aligned.m16n8k16.row.col.f32.bf16.bf16.f32 "
        "{%0,%1,%2,%3}, {%4,%5,%6,%7}, {%8,%9}, {%0,%1,%2,%3};"
        : "+f"(d[0]), "+f"(d[1]), "+f"(d[2]), "+f"(d[3])
        : "r"(a[0]), "r"(a[1]), "r"(a[2]), "r"(a[3]), "r"(b0), "r"(b1));
}

// ------------------------------ MMA-GEMM -------------------------------------
// D[128 px, 192 outch] = (Ahi+Alo)[px,K] @ (Whi+Wlo)[192,K]^T  (drop lo*lo)
#define ASTRIDE 144                 // 64 bf16 = 128B + 16B pad (ldmatrix conflict-free)
#define SA_HI 0
#define SA_LO 18432                 // 128*144
#define SB_HI 36864
#define SB_LO 64512                 // +192*144=27648
#define SMEM1 92160                 // one buffer
#define SMEMT (2 * SMEM1)

__device__ __forceinline__ void load_chunk(
    uint32_t sbuf, const __nv_bfloat16* Ah, const __nv_bfloat16* Al,
    const __nv_bfloat16* Wh, const __nv_bfloat16* Wl, int Ka, int k0, int tid)
{
    #pragma unroll
    for (int i = 0; i < 4; i++) {
        int e = tid + (i << 8); int r = e >> 3, q = e & 7;
        size_t go = (size_t)r * Ka + k0 + (q << 3);
        uint32_t so = r * ASTRIDE + (q << 4);
        cpasync16(sbuf + SA_HI + so, Ah + go);
        cpasync16(sbuf + SA_LO + so, Al + go);
    }
    #pragma unroll
    for (int i = 0; i < 6; i++) {
        int e = tid + (i << 8); int r = e >> 3, q = e & 7;
        size_t go = (size_t)r * Ka + k0 + (q << 3);
        uint32_t so = r * ASTRIDE + (q << 4);
        cpasync16(sbuf + SB_HI + so, Wh + go);
        cpasync16(sbuf + SB_LO + so, Wl + go);
    }
}

__global__ __launch_bounds__(256) void mmagemm_kernel(
    const __nv_bfloat16* __restrict__ Ahi, const __nv_bfloat16* __restrict__ Alo, int Ka,
    const __nv_bfloat16* __restrict__ Whi, const __nv_bfloat16* __restrict__ Wlo,
    float* __restrict__ outF,
    __nv_bfloat16* __restrict__ Ohi, __nv_bfloat16* __restrict__ Olo,
    int outRow, int outOff, int mode)
{
    extern __shared__ char smem[];
    const uint32_t sb = smem_u32(smem);
    const int tid = threadIdx.x;
    const int warp = tid >> 5, lane = tid & 31;
    const int mw = warp >> 1, nw = warp & 1;        // 4 (M) x 2 (N) warps
    const size_t row0 = (size_t)blockIdx.x * 128;   // global pixel row
    const int nChunks = Ka >> 6;

    const __nv_bfloat16* Ah = Ahi + row0 * Ka;
    const __nv_bfloat16* Al = Alo + row0 * Ka;

    float acc[2][12][4] = {};

    // ldmatrix per-lane offsets (relative to buffer base)
    const int grp = lane >> 3, rr = lane & 7;
    uint32_t aoff[2];
    #pragma unroll
    for (int mt = 0; mt < 2; mt++)
        aoff[mt] = SA_HI +
            (uint32_t)(mw * 32 + mt * 16 + rr + (grp & 1) * 8) * ASTRIDE +
            (grp >> 1) * 16;
    const uint32_t boff = SB_HI +
        (uint32_t)(nw * 96 + rr + (grp >> 1) * 8) * ASTRIDE + (grp & 1) * 16;

    load_chunk(sb, Ah, Al, Whi, Wlo, Ka, 0, tid);
    cpcommit();

    for (int ch = 0; ch < nChunks; ch++) {
        const uint32_t buf = sb + (ch & 1) * SMEM1;
        if (ch + 1 < nChunks) {
            load_chunk(sb + ((ch + 1) & 1) * SMEM1, Ah, Al, Whi, Wlo,
                       Ka, (ch + 1) << 6, tid);
            cpcommit();
            cpwait<1>();
        } else {
            cpwait<0>();
        }
        __syncthreads();

        #pragma unroll
        for (int ks = 0; ks < 4; ks++) {
            uint32_t ah[2][4], al[2][4];
            ldsm4(ah[0], buf + aoff[0] + ks * 32);
            ldsm4(ah[1], buf + aoff[1] + ks * 32);
            ldsm4(al[0], buf + aoff[0] + (SA_LO - SA_HI) + ks * 32);
            ldsm4(al[1], buf + aoff[1] + (SA_LO - SA_HI) + ks * 32);
            #pragma unroll
            for (int p = 0; p < 6; p++) {
                uint32_t bh[4], bl[4];
                uint32_t ba = buf + boff + (uint32_t)p * 16 * ASTRIDE + ks * 32;
                ldsm4(bh, ba);
                ldsm4(bl, ba + (SB_LO - SB_HI));
                #pragma unroll
                for (int mt = 0; mt < 2; mt++) {
                    mma16816(acc[mt][2 * p],     ah[mt], bh[0], bh[1]);
                    mma16816(acc[mt][2 * p + 1], ah[mt], bh[2], bh[3]);
                    mma16816(acc[mt][2 * p],     ah[mt], bl[0], bl[1]);
                    mma16816(acc[mt][2 * p + 1], ah[mt], bl[2], bl[3]);
                    mma16816(acc[mt][2 * p],     al[mt], bh[0], bh[1]);
                    mma16816(acc[mt][2 * p + 1], al[mt], bh[2], bh[3]);
                }
            }
        }
        __syncthreads();
    }

    // ---- epilogue ----
    const int mrow = lane >> 2;
    const int ncol = 2 * (lane & 3);
    if (mode == 0) {
        const int bb = (int)(row0 / HW);
        const int px0 = (int)(row0 % HW);
        float* ob = outF + (size_t)bb * DIMC * HW + px0;
        #pragma unroll
        for (int mt = 0; mt < 2; mt++) {
            #pragma unroll
            for (int nt = 0; nt < 12; nt++) {
                int m = mw * 32 + mt * 16 + mrow;
                int n = nw * 96 + nt * 8 + ncol;
                ob[(size_t)n * HW + m]           = acc[mt][nt][0];
                ob[(size_t)(n + 1) * HW + m]     = acc[mt][nt][1];
                ob[(size_t)n * HW + m + 8]       = acc[mt][nt][2];
                ob[(size_t)(n + 1) * HW + m + 8] = acc[mt][nt][3];
            }
        }
    } else {
        #pragma unroll
        for (int mt = 0; mt < 2; mt++) {
            #pragma unroll
            for (int nt = 0; nt < 12; nt++) {
                int m = mw * 32 + mt * 16 + mrow;
                int n = nw * 96 + nt * 8 + ncol;
                #pragma unroll
                for (int half = 0; half < 2; half++) {
                    float f0 = acc[mt][nt][2 * half];
                    float f1 = acc[mt][nt][2 * half + 1];
                    __nv_bfloat16 h0 = __float2bfloat16(f0);
                    __nv_bfloat16 h1 = __float2bfloat16(f1);
                    __nv_bfloat16 l0 = __float2bfloat16(f0 - __bfloat162float(h0));
                    __nv_bfloat16 l1 = __float2bfloat16(f1 - __bfloat162float(h1));
                    size_t rb = (row0 + m + half * 8) * (size_t)outRow + outOff + n;
                    __nv_bfloat162 hv; hv.x = h0; hv.y = h1;
                    __nv_bfloat162 lv; lv.x = l0; lv.y = l1;
                    *reinterpret_cast<__nv_bfloat162*>(Ohi + rb) = hv;
                    *reinterpret_cast<__nv_bfloat162*>(Olo + rb) = lv;
                }
            }
        }
    }
}

// ----------------------- weight convert (hi/lo) -----------------------------
__global__ void convw_kernel(const float* __restrict__ w,
                             __nv_bfloat16* __restrict__ hi,
                             __nv_bfloat16* __restrict__ lo, int n)
{
    int i = blockIdx.x * 256 + threadIdx.x;
    if (i >= n) return;
    float v = w[i];
    __nv_bfloat16 h = __float2bfloat16(v);
    hi[i] = h;
    lo[i] = __float2bfloat16(v - __bfloat162float(h));
}

// -------------------- transpose + hi/lo convert -----------------------------
__global__ __launch_bounds__(256) void tconv_kernel(
    const float* __restrict__ in, __nv_bfloat16* __restrict__ ohi,
    __nv_bfloat16* __restrict__ olo, int C)
{
    const int b = blockIdx.z;
    const int c0 = blockIdx.y * 32, p0 = blockIdx.x * 32;
    __shared__ float t[32][33];
    const int tid = threadIdx.x;
    const int tx = tid & 31, ty = tid >> 5;
    const float* ib = in + (size_t)b * C * HW;
    #pragma unroll
    for (int i = 0; i < 4; i++) {
        int c = ty + i * 8;
        t[c][tx] = ib[(size_t)(c0 + c) * HW + p0 + tx];
    }
    __syncthreads();
    const int t2 = tid & 15, r0 = tid >> 4;
    #pragma unroll
    for (int pass = 0; pass < 2; pass++) {
        int pl = r0 + pass * 16;
        float v0 = t[2 * t2][pl], v1 = t[2 * t2 + 1][pl];
        __nv_bfloat16 h0 = __float2bfloat16(v0), h1 = __float2bfloat16(v1);
        __nv_bfloat16 l0 = __float2bfloat16(v0 - __bfloat162float(h0));
        __nv_bfloat16 l1 = __float2bfloat16(v1 - __bfloat162float(h1));
        size_t rb = ((size_t)b * HW + p0 + pl) * C + c0 + 2 * t2;
        __nv_bfloat162 hv; hv.x = h0; hv.y = h1;
        __nv_bfloat162 lv; lv.x = l0; lv.y = l1;
        *reinterpret_cast<__nv_bfloat162*>(ohi + rb) = hv;
        *reinterpret_cast<__nv_bfloat162*>(olo + rb) = lv;
    }
}

// ------------------------------ fp32 SGEMM (qkv only) ------------------------
#define BM 64
#define BN 128
#define BKK 16

__global__ __launch_bounds__(256) void gemm_kernel(
    const float* __restrict__ Wt, const float* __restrict__ In,
    float* __restrict__ Out, int K, int N, size_t inBS, size_t outBS)
{
    const int b = blockIdx.z;
    const float* Ib = In + (size_t)b * inBS;
    float* Ob = Out + (size_t)b * outBS;
    const int m0 = blockIdx.y * BM;
    const int n0 = blockIdx.x * BN;

    __shared__ float Ws[BKK][BM];
    __shared__ float Is[BKK][BN];

    const int tid = threadIdx.x;
    const int tx = tid & 15;
    const int ty = tid >> 4;

    float acc[4][8] = {};

    for (int k0 = 0; k0 < K; k0 += BKK) {
        #pragma unroll
        for (int i = 0; i < 4; i++) {
            int e = tid + i * 256;
            int m = e >> 4, k = e & 15;
            Ws[k][m] = Wt[(size_t)(m0 + m) * K + k0 + k];
        }
        #pragma unroll
        for (int i = 0; i < 2; i++) {
            int e = tid + i * 256;
            int k = e >> 5, n4 = e & 31;
            float4 v = *reinterpret_cast<const float4*>(
                &Ib[(size_t)(k0 + k) * N + n0 + n4 * 4]);
            *reinterpret_cast<float4*>(&Is[k][n4 * 4]) = v;
        }
        __syncthreads();
        #pragma unroll
        for (int k = 0; k < BKK; k++) {
            float4 av = *reinterpret_cast<const float4*>(&Ws[k][ty * 4]);
            float4 b0 = *reinterpret_cast<const float4*>(&Is[k][tx * 8]);
            float4 b1 = *reinterpret_cast<const float4*>(&Is[k][tx * 8 + 4]);
            float a[4] = {av.x, av.y, av.z, av.w};
            float bb[8] = {b0.x, b0.y, b0.z, b0.w, b1.x, b1.y, b1.z, b1.w};
            #pragma unroll
            for (int i = 0; i < 4; i++)
                #pragma unroll
                for (int j = 0; j < 8; j++)
                    acc[i][j] = fmaf(a[i], bb[j], acc[i][j]);
        }
        __syncthreads();
    }
    #pragma unroll
    for (int i = 0; i < 4; i++) {
        size_t row = (size_t)(m0 + ty * 4 + i) * N + n0 + tx * 8;
        *reinterpret_cast<float4*>(&Ob[row]) =
            make_float4(acc[i][0], acc[i][1], acc[i][2], acc[i][3]);
        *reinterpret_cast<float4*>(&Ob[row + 4]) =
            make_float4(acc[i][4], acc[i][5], acc[i][6], acc[i][7]);
    }
}

// --------------------- fused strip conv + 3x3 depthwise ---------------------
__global__ __launch_bounds__(256) void highpre_kernel(
    const float* __restrict__ x,
    const float* __restrict__ w_dww, const float* __restrict__ b_dww,
    const float* __restrict__ w_dwh, const float* __restrict__ b_dwh,
    const float* __restrict__ w_dwhw, const float* __restrict__ b_dwhw)
{
    const int zc = blockIdx.z;
    const int b = zc / 384, cp = zc % 384;
    const bool horiz = (cp < DIMC);
    const int c = horiz ? cp : cp - DIMC;
    const int y0 = blockIdx.y * 32, x0 = blockIdx.x * 32;
    const float* xp = x + ((size_t)b * DIMC + c) * HW;

    __shared__ float xs[44][44];
    __shared__ float ss[34][36];
    __shared__ float wk[11], w3[9];

    const int tid = threadIdx.x;
    if (tid < 11) wk[tid] = horiz ? w_dww[c * 11 + tid] : w_dwh[c * 11 + tid];
    if (tid < 9)  w3[tid] = w_dwhw[cp * 9 + tid];

    for (int i = tid; i < 44 * 44; i += 256) {
        int r = i / 44, cc = i % 44;
        int gy = y0 - 6 + r, gx = x0 - 6 + cc;
        float v = 0.f;
        if (gy >= 0 && gy < HH && gx >= 0 && gx < WW) v = xp[gy * WW + gx];
        xs[r][cc] = v;
    }
    __syncthreads();

    const float bs = horiz ? b_dww[c] : b_dwh[c];
    for (int i = tid; i < 34 * 34; i += 256) {
        int r = i / 34, cc = i % 34;
        int gy = y0 - 1 + r, gx = x0 - 1 + cc;
        float v = 0.f;
        if (gy >= 0 && gy < HH && gx >= 0 && gx < WW) {
            float s = bs;
            if (horiz) {
                #pragma unroll
                for (int k = 0; k < 11; k++) s = fmaf(xs[r + 5][cc + k], wk[k], s);
            } else {
                #pragma unroll
                for (int k = 0; k < 11; k++) s = fmaf(xs[r + k][cc + 5], wk[k], s);
            }
            v = s;
        }
        ss[r][cc] = v;
    }
    __syncthreads();

    const float b3 = b_dwhw[cp];
    float* op = g_hcatdw + ((size_t)b * 384 + cp) * HW;
    const int tx = tid & 31, tyy = tid >> 5;
    #pragma unroll
    for (int rr = 0; rr < 4; rr++) {
        int oy = tyy + rr * 8;
        float s = b3;
        #pragma unroll
        for (int ky = 0; ky < 3; ky++)
            #pragma unroll
            for (int kx = 0; kx < 3; kx++)
                s = fmaf(ss[oy + ky][tx + kx], w3[ky * 3 + kx], s);
        op[(y0 + oy) * WW + x0 + tx] = s;
    }
}

// ----------------------------- avg pool 8x8 ---------------------------------
__global__ void pool_kernel(const float* __restrict__ x)
{
    int idx = blockIdx.x * 256 + threadIdx.x;
    if (idx >= BATCH * DIMC * PD) return;
    int p = idx % PD; int bc = idx / PD;
    int yd = p / WD, xd = p % WD;
    const float* xp = x + (size_t)bc * HW;
    float s = 0.f;
    #pragma unroll
    for (int i = 0; i < 8; i++)
        #pragma unroll
        for (int j = 0; j < 8; j++)
            s += xp[(yd * 8 + i) * WW + xd * 8 + j];
    g_xdown[idx] = s * (1.f / 64.f);
}

// ------------------------- 3x3 depthwise (32x32) ----------------------------
__global__ __launch_bounds__(256) void dw3x3_small_kernel(const float* __restrict__ w)
{
    const int zc = blockIdx.x;
    const int c = zc % 576;
    __shared__ float xs[34][34];
    __shared__ float w3[9];
    const int tid = threadIdx.x;
    const float* ip = g_qkv + (size_t)zc * PD;
    if (tid < 9) w3[tid] = w[c * 9 + tid];
    for (int i = tid; i < 34 * 34; i += 256) {
        int r = i / 34, cc = i % 34;
        int gy = r - 1, gx = cc - 1;
        xs[r][cc] = (gy >= 0 && gy < HD && gx >= 0 && gx < WD) ? ip[gy * WD + gx] : 0.f;
    }
    __syncthreads();
    const int tx = tid & 31, ty = tid >> 5;
    float* op = g_qkvdw + (size_t)zc * PD;
    #pragma unroll
    for (int rr = 0; rr < 4; rr++) {
        int oy = ty + rr * 8;
        float s = 0.f;
        #pragma unroll
        for (int ky = 0; ky < 3; ky++)
            #pragma unroll
            for (int kx = 0; kx < 3; kx++)
                s = fmaf(xs[oy + ky][tx + kx], w3[ky * 3 + kx], s);
        op[oy * WD + tx] = s;
    }
}

// ------------------- 3x3 depthwise (256x256) * gate -------------------------
__global__ __launch_bounds__(256) void dw3x3_gate_kernel(const float* __restrict__ w)
{
    const int zc = blockIdx.z;
    const int b = zc / DIMC, c = zc % DIMC;
    const int y0 = blockIdx.y * 32, x0 = blockIdx.x * 32;
    const float* ip = g_t4 + (size_t)zc * HW;
    __shared__ float xs[34][34];
    __shared__ float w3[9];
    const int tid = threadIdx.x;
    if (tid < 9) w3[tid] = w[c * 9 + tid];
    for (int i = tid; i < 34 * 34; i += 256) {
        int r = i / 34, cc = i % 34;
        int gy = y0 - 1 + r, gx = x0 - 1 + cc;
        xs[r][cc] = (gy >= 0 && gy < HH && gx >= 0 && gx < WW) ? ip[gy * WW + gx] : 0.f;
    }
    __syncthreads();
    const float g = g_gate[b * DIMC + c];
    float* op = g_vfull + (size_t)zc * HW;
    const int tx = tid & 31, ty = tid >> 5;
    #pragma unroll
    for (int rr = 0; rr < 4; rr++) {
        int oy = ty + rr * 8;
        float s = 0.f;
        #pragma unroll
        for (int ky = 0; ky < 3; ky++)
            #pragma unroll
            for (int kx = 0; kx < 3; kx++)
                s = fmaf(xs[oy + ky][tx + kx], w3[ky * 3 + kx], s);
        op[(y0 + oy) * WW + x0 + tx] = g * s;
    }
}

// --------------- attention Gram + softmax (coalesced, chunked) --------------
__global__ void attn_kernel2(const float* __restrict__ temp)
{
    const int bh = blockIdx.x;
    const int b = bh / HEADS, h = bh % HEADS;
    const float* q = g_qkvdw + ((size_t)b * 576 + h * CH) * PD;
    const float* kk = g_qkvdw + ((size_t)b * 576 + DIMC + h * CH) * PD;

    __shared__ float qs[CH][65], ks[CH][65];
    __shared__ float qn[CH], kn[CH], sm[CH][CH];
    const int tid = threadIdx.x;            // 576
    const int c = tid / CH, d = tid % CH;

    float acc = 0.f, accq = 0.f, acck = 0.f;
    for (int chn = 0; chn < 16; chn++) {
        #pragma unroll
        for (int i = 0; i < 3; i++) {
            int e = tid + i * 576;
            if (e < CH * 64) {
                int r = e >> 6, cc = e & 63;
                qs[r][cc] = q[(size_t)r * PD + chn * 64 + cc];
                ks[r][cc] = kk[(size_t)r * PD + chn * 64 + cc];
            }
        }
        __syncthreads();
        #pragma unroll 8
        for (int i = 0; i < 64; i++)
            acc = fmaf(qs[c][i], ks[d][i], acc);
        if (c == d) {
            #pragma unroll 8
            for (int i = 0; i < 64; i++) {
                accq = fmaf(qs[c][i], qs[c][i], accq);
                acck = fmaf(ks[c][i], ks[c][i], acck);
            }
        }
        __syncthreads();
    }
    if (c == d) {
        qn[c] = fmaxf(sqrtf(accq), 1e-12f);
        kn[c] = fmaxf(sqrtf(acck), 1e-12f);
    }
    __syncthreads();
    sm[c][d] = acc / (qn[c] * kn[d]) * temp[h];
    __syncthreads();
    if (tid < CH) {
        float m = -1e30f;
        for (int j = 0; j < CH; j++) m = fmaxf(m, sm[tid][j]);
        float e[CH]; float ssum = 0.f;
        for (int j = 0; j < CH; j++) { e[j] = expf(sm[tid][j] - m); ssum += e[j]; }
        float inv = 1.f / ssum;
        for (int j = 0; j < CH; j++)
            g_attn[((size_t)bh * CH + tid) * CH + j] = e[j] * inv;
    }
}

// ------------------------------ v gate (coalesced) ---------------------------
__global__ void vgate_kernel2(const float* __restrict__ w2, const float* __restrict__ w3)
{
    const int b = blockIdx.x;
    const float* v = g_qkvdw + ((size_t)b * 576 + 2 * DIMC) * PD;
    __shared__ float vmax[DIMC], vavg[DIMC];
    const int tid = threadIdx.x;   // 256
    const int wid = tid >> 5, lane = tid & 31;
    for (int c = wid; c < DIMC; c += 8) {
        const float* p = v + (size_t)c * PD;
        float m = -1e30f, s = 0.f;
        for (int i = lane; i < PD; i += 32) { float vv = p[i]; m = fmaxf(m, vv); s += vv; }
        #pragma unroll
        for (int off = 16; off; off >>= 1) {
            m = fmaxf(m, __shfl_xor_sync(0xFFFFFFFF, m, off));
            s += __shfl_xor_sync(0xFFFFFFFF, s, off);
        }
        if (lane == 0) { vmax[c] = m; vavg[c] = s * (1.f / (float)PD); }
    }
    __syncthreads();
    if (tid < DIMC) {
        float g = 0.f;
        for (int c = 0; c < DIMC; c++)
            g = fmaf(w2[tid * DIMC + c], vmax[c], fmaf(w3[tid * DIMC + c], vavg[c], g));
        g_gate[b * DIMC + tid] = g;
    }
}

// --------------- attention apply -> cat (pixel-major hi/lo) -----------------
__global__ __launch_bounds__(256) void attnapply_kernel2()
{
    const int b = blockIdx.z, h = blockIdx.y;
    const int p = blockIdx.x * 256 + threadIdx.x;
    __shared__ float a[CH][CH];
    const int tid = threadIdx.x;
    for (int i = tid; i < CH * CH; i += 256)
        a[i / CH][i % CH] = g_attn[(size_t)(b * HEADS + h) * CH * CH + i];
    __syncthreads();

    const float* vb = g_vfull + ((size_t)b * DIMC + h * CH) * HW + p;
    float v[CH];
    #pragma unroll
    for (int d = 0; d < CH; d++) v[d] = vb[(size_t)d * HW];

    float s[CH];
    #pragma unroll
    for (int c = 0; c < CH; c++) {
        float t = 0.f;
        #pragma unroll
        for (int d = 0; d < CH; d++) t = fmaf(a[c][d], v[d], t);
        s[c] = t;
    }
    size_t rb = ((size_t)b * HW + p) * 384 + DIMC + h * CH;
    #pragma unroll
    for (int c = 0; c < CH; c += 2) {
        __nv_bfloat16 h0 = __float2bfloat16(s[c]), h1 = __float2bfloat16(s[c + 1]);
        __nv_bfloat16 l0 = __float2bfloat16(s[c] - __bfloat162float(h0));
        __nv_bfloat16 l1 = __float2bfloat16(s[c + 1] - __bfloat162float(h1));
        __nv_bfloat162 hv; hv.x = h0; hv.y = h1;
        __nv_bfloat162 lv; lv.x = l0; lv.y = l1;
        *reinterpret_cast<__nv_bfloat162*>(g_cat_hi + rb + c) = hv;
        *reinterpret_cast<__nv_bfloat162*>(g_cat_lo + rb + c) = lv;
    }
}

// ------------------------------- launch -------------------------------------
extern "C" void kernel_launch(void* const* d_in, const int* in_sizes, int n_in,
                              void* d_out, int out_size)
{
    const float* x        = (const float*)d_in[0];
    const float* w_dww    = (const float*)d_in[1];
    const float* b_dww    = (const float*)d_in[2];
    const float* w_dwh    = (const float*)d_in[3];
    const float* b_dwh    = (const float*)d_in[4];
    const float* w_dwhw   = (const float*)d_in[5];
    const float* b_dwhw   = (const float*)d_in[6];
    const float* w_conv1  = (const float*)d_in[7];
    const float* w_qkv    = (const float*)d_in[8];
    const float* w_qkvdw  = (const float*)d_in[9];
    const float* w_conv2  = (const float*)d_in[10];
    const float* w_conv3  = (const float*)d_in[11];
    const float* w_conv4a = (const float*)d_in[12];
    const float* w_conv4b = (const float*)d_in[13];
    const float* w_proj   = (const float*)d_in[14];
    const float* temp     = (const float*)d_in[15];
    float* out = (float*)d_out;

    float *p_hcatdw, *p_t4, *p_xdown, *p_qkv;
    __nv_bfloat16 *p_hch, *p_hcl, *p_xh, *p_xl, *p_cath, *p_catl;
    __nv_bfloat16 *p_w1h, *p_w1l, *p_w4h, *p_w4l, *p_wph, *p_wpl;
    cudaGetSymbolAddress((void**)&p_hcatdw, g_hcatdw);
    cudaGetSymbolAddress((void**)&p_t4,     g_t4);
    cudaGetSymbolAddress((void**)&p_xdown,  g_xdown);
    cudaGetSymbolAddress((void**)&p_qkv,    g_qkv);
    cudaGetSymbolAddress((void**)&p_hch,    g_hc_hi);
    cudaGetSymbolAddress((void**)&p_hcl,    g_hc_lo);
    cudaGetSymbolAddress((void**)&p_xh,     g_x_hi);
    cudaGetSymbolAddress((void**)&p_xl,     g_x_lo);
    cudaGetSymbolAddress((void**)&p_cath,   g_cat_hi);
    cudaGetSymbolAddress((void**)&p_catl,   g_cat_lo);
    cudaGetSymbolAddress((void**)&p_w1h,    g_w1h);
    cudaGetSymbolAddress((void**)&p_w1l,    g_w1l);
    cudaGetSymbolAddress((void**)&p_w4h,    g_w4h);
    cudaGetSymbolAddress((void**)&p_w4l,    g_w4l);
    cudaGetSymbolAddress((void**)&p_wph,    g_wph);
    cudaGetSymbolAddress((void**)&p_wpl,    g_wpl);

    cudaFuncSetAttribute(mmagemm_kernel,
                         cudaFuncAttributeMaxDynamicSharedMemorySize, SMEMT);

    // weight splits
    convw_kernel<<<(192 * 384 + 255) / 256, 256>>>(w_conv1, p_w1h, p_w1l, 192 * 384);
    convw_kernel<<<(192 * 192 + 255) / 256, 256>>>(w_conv4a, p_w4h, p_w4l, 192 * 192);
    convw_kernel<<<(192 * 384 + 255) / 256, 256>>>(w_proj, p_wph, p_wpl, 192 * 384);

    // ---- low branch (small) ----
    pool_kernel<<<(BATCH * DIMC * PD + 255) / 256, 256>>>(x);
    gemm_kernel<<<dim3(PD / BN, 576 / BM, BATCH), 256>>>(
        w_qkv, p_xdown, p_qkv, DIMC, PD, (size_t)DIMC * PD, (size_t)576 * PD);
    dw3x3_small_kernel<<<BATCH * 576, 256>>>(w_qkvdw);
    attn_kernel2<<<BATCH * HEADS, 576>>>(temp);
    vgate_kernel2<<<BATCH, 256>>>(w_conv2, w_conv3);

    // ---- high branch ----
    highpre_kernel<<<dim3(WW / 32, HH / 32, BATCH * 384), 256>>>(
        x, w_dww, b_dww, w_dwh, b_dwh, w_dwhw, b_dwhw);
    tconv_kernel<<<dim3(HW / 32, 384 / 32, BATCH), 256>>>(p_hcatdw, p_hch, p_hcl, 384);
    tconv_kernel<<<dim3(HW / 32, DIMC / 32, BATCH), 256>>>(x, p_xh, p_xl, DIMC);

    // conv1 -> cat[:,0:192] (pixel-major hi/lo), M rows = B*HW
    mmagemm_kernel<<<(BATCH * HW) / 128, 256, SMEMT>>>(
        p_hch, p_hcl, 384, p_w1h, p_w1l,
        nullptr, p_cath, p_catl, 384, 0, 1);

    // conv4a -> t4 (fp32 ch-major)
    mmagemm_kernel<<<(BATCH * HW) / 128, 256, SMEMT>>>(
        p_xh, p_xl, DIMC, p_w4h, p_w4l,
        p_t4, nullptr, nullptr, 0, 0, 0);

    dw3x3_gate_kernel<<<dim3(WW / 32, HH / 32, BATCH * DIMC), 256>>>(w_conv4b);
    attnapply_kernel2<<<dim3(HW / 256, HEADS, BATCH), 256>>>();

    // proj -> out (fp32 ch-major)
    mmagemm_kernel<<<(BATCH * HW) / 128, 256, SMEMT>>>(
        p_cath, p_catl, 384, p_wph, p_wpl,
        out, nullptr, nullptr, 0, 0, 0);
}

// round 6
// speedup vs baseline: 2.7435x; 1.2628x over previous
#include <cuda_runtime.h>
#include <cuda_bf16.h>
#include <cstdint>

// ---------------------------------------------------------------------------
// HybridAttention — round 5: R4 + dwattn a2-fill bugfix.
// ch-major fp32 everywhere; GEMM does hi/lo bf16 split on the fly
// (ldmatrix.trans A); dw-gate + attn-apply fused.
// ---------------------------------------------------------------------------

#define DIMC   192
#define HEADS  8
#define CH     24
#define HH     256
#define WW     256
#define HW     65536
#define HD     32
#define WD     32
#define PD     1024
#define BATCH  4

// ------------------------- scratch (static device) -------------------------
__device__ float g_hcatdw[(size_t)BATCH * 384 * HW];   // strip+3x3 dw (ch-major)
__device__ float g_cat   [(size_t)BATCH * 384 * HW];   // [high | low] ch-major
__device__ float g_t4    [(size_t)BATCH * DIMC * HW];  // conv4a out
__device__ float g_xdown [(size_t)BATCH * DIMC * PD];
__device__ float g_qkv   [(size_t)BATCH * 576 * PD];
__device__ float g_qkvdw [(size_t)BATCH * 576 * PD];
__device__ float g_attn  [(size_t)BATCH * HEADS * CH * CH];
__device__ float g_gate  [(size_t)BATCH * DIMC];
// weights hi/lo (row-major [outch][K])
__device__ __nv_bfloat16 g_w1h[192 * 384], g_w1l[192 * 384];
__device__ __nv_bfloat16 g_w4h[192 * 192], g_w4l[192 * 192];
__device__ __nv_bfloat16 g_wph[192 * 384], g_wpl[192 * 384];

// --------------------------- ptx helpers (sm_80 ISA) ------------------------
__device__ __forceinline__ uint32_t smem_u32(const void* p) {
    uint32_t a;
    asm("{ .reg .u64 t; cvta.to.shared.u64 t, %1; cvt.u32.u64 %0, t; }"
        : "=r"(a) : "l"(p));
    return a;
}
__device__ __forceinline__ void cpasync16(uint32_t saddr, const void* gaddr) {
    asm volatile("cp.async.cg.shared.global [%0], [%1], 16;"
                 :: "r"(saddr), "l"(gaddr));
}
__device__ __forceinline__ void cpcommit() {
    asm volatile("cp.async.commit_group;" ::: "memory");
}
template<int N> __device__ __forceinline__ void cpwait() {
    asm volatile("cp.async.wait_group %0;" :: "n"(N) : "memory");
}
__device__ __forceinline__ void ldsm4(uint32_t* r, uint32_t addr) {
    asm volatile("ldmatrix.sync.aligned.m8n8.x4.shared.b16 {%0,%1,%2,%3}, [%4];"
        : "=r"(r[0]), "=r"(r[1]), "=r"(r[2]), "=r"(r[3]) : "r"(addr));
}
__device__ __forceinline__ void ldsm4t(uint32_t* r, uint32_t addr) {
    asm volatile("ldmatrix.sync.aligned.m8n8.x4.trans.shared.b16 {%0,%1,%2,%3}, [%4];"
        : "=r"(r[0]), "=r"(r[1]), "=r"(r[2]), "=r"(r[3]) : "r"(addr));
}
__device__ __forceinline__ void mma16816(float* d, const uint32_t* a,
                                         uint32_t b0, uint32_t b1) {
    asm volatile(
        "mma.sync.aligned.m16n8k16.row.col.f32.bf16.bf16.f32 "
        "{%0,%1,%2,%3}, {%4,%5,%6,%7}, {%8,%9}, {%0,%1,%2,%3};"
        : "+f"(d[0]), "+f"(d[1]), "+f"(d[2]), "+f"(d[3])
        : "r"(a[0]), "r"(a[1]), "r"(a[2]), "r"(a[3]), "r"(b0), "r"(b1));
}
__device__ __forceinline__ uint32_t pk2(float a, float b) {
    __nv_bfloat162 t; t.x = __float2bfloat16(a); t.y = __float2bfloat16(b);
    return *reinterpret_cast<uint32_t*>(&t);
}

// ------------------------------ MMA-GEMM -------------------------------------
// D[128 px, 192 outch] = A[K, px]^T @ (Whi+Wlo)[192,K]^T, A fp32 split on load.
#define ASTR  272      // 128 px bf16 = 256B + 16 pad
#define BSTR  144      // 64 k bf16 = 128B + 16 pad
#define ATH   0
#define ATL   17408    // 64*272
#define BH    34816
#define BL    62464    // +192*144
#define SMEM1 90112
#define SMEMT (2 * SMEM1)

__device__ __forceinline__ void lda_regs(float4* r, const float* Ab, int k0, int tid) {
    #pragma unroll
    for (int i = 0; i < 8; i++) {
        int e = tid + (i << 8); int k = e >> 5, q = e & 31;
        r[i] = *reinterpret_cast<const float4*>(Ab + (size_t)(k0 + k) * HW + (q << 2));
    }
}
__device__ __forceinline__ void cvt_sts(const float4* r, char* smem,
                                        uint32_t bufOff, int tid) {
    #pragma unroll
    for (int i = 0; i < 8; i++) {
        int e = tid + (i << 8); int k = e >> 5, q = e & 31;
        float4 f = r[i];
        uint32_t so = bufOff + (uint32_t)k * ASTR + (q << 3);
        uint2 hv, lv;
        hv.x = pk2(f.x, f.y); hv.y = pk2(f.z, f.w);
        float rx = f.x - __bfloat162float(__float2bfloat16(f.x));
        float ry = f.y - __bfloat162float(__float2bfloat16(f.y));
        float rz = f.z - __bfloat162float(__float2bfloat16(f.z));
        float rw = f.w - __bfloat162float(__float2bfloat16(f.w));
        lv.x = pk2(rx, ry); lv.y = pk2(rz, rw);
        *reinterpret_cast<uint2*>(smem + so + ATH) = hv;
        *reinterpret_cast<uint2*>(smem + so + ATL - ATH) = lv;
    }
}
__device__ __forceinline__ void ldb_async(uint32_t sbuf,
    const __nv_bfloat16* Wh, const __nv_bfloat16* Wl, int Ka, int k0, int tid) {
    #pragma unroll
    for (int i = 0; i < 6; i++) {
        int e = tid + (i << 8); int r = e >> 3, q = e & 7;
        size_t go = (size_t)r * Ka + k0 + (q << 3);
        uint32_t so = r * BSTR + (q << 4);
        cpasync16(sbuf + BH + so, Wh + go);
        cpasync16(sbuf + BL + so, Wl + go);
    }
}

__global__ __launch_bounds__(256, 1) void fgemm_kernel(
    const float* __restrict__ In, int Ka,
    const __nv_bfloat16* __restrict__ Whi, const __nv_bfloat16* __restrict__ Wlo,
    float* __restrict__ Out, int chTot, int outOff)
{
    extern __shared__ char smem[];
    const uint32_t sb = smem_u32(smem);
    const int tid = threadIdx.x;
    const int warp = tid >> 5, lane = tid & 31;
    const int mw = warp >> 1, nw = warp & 1;        // 4 (M) x 2 (N) warps
    const int b = blockIdx.z;
    const int px0 = blockIdx.x * 128;
    const int nChunks = Ka >> 6;

    const float* Ab = In + (size_t)b * Ka * HW + px0;

    float acc[2][12][4] = {};

    const int grp = lane >> 3, rr = lane & 7;
    uint32_t aoff[2];
    #pragma unroll
    for (int mt = 0; mt < 2; mt++)
        aoff[mt] = (uint32_t)((grp >> 1) * 8 + rr) * ASTR +
                   (uint32_t)(mw * 32 + mt * 16 + (grp & 1) * 8) * 2;
    const uint32_t boff = (uint32_t)(nw * 96 + rr + (grp >> 1) * 8) * BSTR +
                          (grp & 1) * 16;

    float4 ar[8];
    lda_regs(ar, Ab, 0, tid);
    ldb_async(sb, Whi, Wlo, Ka, 0, tid);
    cpcommit();

    for (int ch = 0; ch < nChunks; ch++) {
        const uint32_t bufo = (uint32_t)(ch & 1) * SMEM1;
        cvt_sts(ar, smem + bufo, ATH, tid);
        if (ch + 1 < nChunks) {
            lda_regs(ar, Ab, (ch + 1) << 6, tid);
            ldb_async(sb + ((ch + 1) & 1) * SMEM1, Whi, Wlo, Ka, (ch + 1) << 6, tid);
            cpcommit();
            cpwait<1>();
        } else {
            cpwait<0>();
        }
        __syncthreads();

        const uint32_t buf = sb + bufo;
        #pragma unroll
        for (int ks = 0; ks < 4; ks++) {
            uint32_t ah[2][4], al[2][4];
            ldsm4t(ah[0], buf + ATH + aoff[0] + ks * (16 * ASTR));
            ldsm4t(ah[1], buf + ATH + aoff[1] + ks * (16 * ASTR));
            ldsm4t(al[0], buf + ATL + aoff[0] + ks * (16 * ASTR));
            ldsm4t(al[1], buf + ATL + aoff[1] + ks * (16 * ASTR));
            #pragma unroll
            for (int p = 0; p < 6; p++) {
                uint32_t bh[4], bl[4];
                uint32_t ba = buf + boff + (uint32_t)p * 16 * BSTR + ks * 32;
                ldsm4(bh, ba + BH);
                ldsm4(bl, ba + BL);
                #pragma unroll
                for (int mt = 0; mt < 2; mt++) {
                    mma16816(acc[mt][2 * p],     ah[mt], bh[0], bh[1]);
                    mma16816(acc[mt][2 * p + 1], ah[mt], bh[2], bh[3]);
                    mma16816(acc[mt][2 * p],     ah[mt], bl[0], bl[1]);
                    mma16816(acc[mt][2 * p + 1], ah[mt], bl[2], bl[3]);
                    mma16816(acc[mt][2 * p],     al[mt], bh[0], bh[1]);
                    mma16816(acc[mt][2 * p + 1], al[mt], bh[2], bh[3]);
                }
            }
        }
        __syncthreads();
    }

    // ---- epilogue: fp32 ch-major ----
    const int mrow = lane >> 2;
    const int ncol = 2 * (lane & 3);
    float* ob = Out + ((size_t)b * chTot + outOff) * HW + px0;
    #pragma unroll
    for (int mt = 0; mt < 2; mt++) {
        #pragma unroll
        for (int nt = 0; nt < 12; nt++) {
            int m = mw * 32 + mt * 16 + mrow;
            int n = nw * 96 + nt * 8 + ncol;
            ob[(size_t)n * HW + m]           = acc[mt][nt][0];
            ob[(size_t)(n + 1) * HW + m]     = acc[mt][nt][1];
            ob[(size_t)n * HW + m + 8]       = acc[mt][nt][2];
            ob[(size_t)(n + 1) * HW + m + 8] = acc[mt][nt][3];
        }
    }
}

// ----------------------- weight convert (hi/lo) -----------------------------
__global__ void convw_kernel(const float* __restrict__ w,
                             __nv_bfloat16* __restrict__ hi,
                             __nv_bfloat16* __restrict__ lo, int n)
{
    int i = blockIdx.x * 256 + threadIdx.x;
    if (i >= n) return;
    float v = w[i];
    __nv_bfloat16 h = __float2bfloat16(v);
    hi[i] = h;
    lo[i] = __float2bfloat16(v - __bfloat162float(h));
}

// ------------------------------ fp32 SGEMM (qkv only) ------------------------
#define BM 64
#define BN 128
#define BKK 16

__global__ __launch_bounds__(256) void gemm_kernel(
    const float* __restrict__ Wt, const float* __restrict__ In,
    float* __restrict__ Out, int K, int N, size_t inBS, size_t outBS)
{
    const int b = blockIdx.z;
    const float* Ib = In + (size_t)b * inBS;
    float* Ob = Out + (size_t)b * outBS;
    const int m0 = blockIdx.y * BM;
    const int n0 = blockIdx.x * BN;

    __shared__ float Ws[BKK][BM];
    __shared__ float Is[BKK][BN];

    const int tid = threadIdx.x;
    const int tx = tid & 15;
    const int ty = tid >> 4;

    float acc[4][8] = {};

    for (int k0 = 0; k0 < K; k0 += BKK) {
        #pragma unroll
        for (int i = 0; i < 4; i++) {
            int e = tid + i * 256;
            int m = e >> 4, k = e & 15;
            Ws[k][m] = Wt[(size_t)(m0 + m) * K + k0 + k];
        }
        #pragma unroll
        for (int i = 0; i < 2; i++) {
            int e = tid + i * 256;
            int k = e >> 5, n4 = e & 31;
            float4 v = *reinterpret_cast<const float4*>(
                &Ib[(size_t)(k0 + k) * N + n0 + n4 * 4]);
            *reinterpret_cast<float4*>(&Is[k][n4 * 4]) = v;
        }
        __syncthreads();
        #pragma unroll
        for (int k = 0; k < BKK; k++) {
            float4 av = *reinterpret_cast<const float4*>(&Ws[k][ty * 4]);
            float4 b0 = *reinterpret_cast<const float4*>(&Is[k][tx * 8]);
            float4 b1 = *reinterpret_cast<const float4*>(&Is[k][tx * 8 + 4]);
            float a[4] = {av.x, av.y, av.z, av.w};
            float bb[8] = {b0.x, b0.y, b0.z, b0.w, b1.x, b1.y, b1.z, b1.w};
            #pragma unroll
            for (int i = 0; i < 4; i++)
                #pragma unroll
                for (int j = 0; j < 8; j++)
                    acc[i][j] = fmaf(a[i], bb[j], acc[i][j]);
        }
        __syncthreads();
    }
    #pragma unroll
    for (int i = 0; i < 4; i++) {
        size_t row = (size_t)(m0 + ty * 4 + i) * N + n0 + tx * 8;
        *reinterpret_cast<float4*>(&Ob[row]) =
            make_float4(acc[i][0], acc[i][1], acc[i][2], acc[i][3]);
        *reinterpret_cast<float4*>(&Ob[row + 4]) =
            make_float4(acc[i][4], acc[i][5], acc[i][6], acc[i][7]);
    }
}

// --------------------- fused strip conv + 3x3 depthwise ---------------------
__global__ __launch_bounds__(256) void highpre_kernel(
    const float* __restrict__ x,
    const float* __restrict__ w_dww, const float* __restrict__ b_dww,
    const float* __restrict__ w_dwh, const float* __restrict__ b_dwh,
    const float* __restrict__ w_dwhw, const float* __restrict__ b_dwhw)
{
    const int zc = blockIdx.z;
    const int b = zc / 384, cp = zc % 384;
    const bool horiz = (cp < DIMC);
    const int c = horiz ? cp : cp - DIMC;
    const int y0 = blockIdx.y * 32, x0 = blockIdx.x * 32;
    const float* xp = x + ((size_t)b * DIMC + c) * HW;

    __shared__ float xs[44][44];
    __shared__ float ss[34][36];
    __shared__ float wk[11], w3[9];

    const int tid = threadIdx.x;
    if (tid < 11) wk[tid] = horiz ? w_dww[c * 11 + tid] : w_dwh[c * 11 + tid];
    if (tid < 9)  w3[tid] = w_dwhw[cp * 9 + tid];

    for (int i = tid; i < 44 * 44; i += 256) {
        int r = i / 44, cc = i % 44;
        int gy = y0 - 6 + r, gx = x0 - 6 + cc;
        float v = 0.f;
        if (gy >= 0 && gy < HH && gx >= 0 && gx < WW) v = xp[gy * WW + gx];
        xs[r][cc] = v;
    }
    __syncthreads();

    const float bs = horiz ? b_dww[c] : b_dwh[c];
    for (int i = tid; i < 34 * 34; i += 256) {
        int r = i / 34, cc = i % 34;
        int gy = y0 - 1 + r, gx = x0 - 1 + cc;
        float v = 0.f;
        if (gy >= 0 && gy < HH && gx >= 0 && gx < WW) {
            float s = bs;
            if (horiz) {
                #pragma unroll
                for (int k = 0; k < 11; k++) s = fmaf(xs[r + 5][cc + k], wk[k], s);
            } else {
                #pragma unroll
                for (int k = 0; k < 11; k++) s = fmaf(xs[r + k][cc + 5], wk[k], s);
            }
            v = s;
        }
        ss[r][cc] = v;
    }
    __syncthreads();

    const float b3 = b_dwhw[cp];
    float* op = g_hcatdw + ((size_t)b * 384 + cp) * HW;
    const int tx = tid & 31, tyy = tid >> 5;
    #pragma unroll
    for (int rr = 0; rr < 4; rr++) {
        int oy = tyy + rr * 8;
        float s = b3;
        #pragma unroll
        for (int ky = 0; ky < 3; ky++)
            #pragma unroll
            for (int kx = 0; kx < 3; kx++)
                s = fmaf(ss[oy + ky][tx + kx], w3[ky * 3 + kx], s);
        op[(y0 + oy) * WW + x0 + tx] = s;
    }
}

// ----------------------------- avg pool 8x8 (float4) -------------------------
__global__ void pool_kernel(const float* __restrict__ x)
{
    int idx = blockIdx.x * 256 + threadIdx.x;
    if (idx >= BATCH * DIMC * PD) return;
    int p = idx % PD; int bc = idx / PD;
    int yd = p / WD, xd = p % WD;
    const float* xp = x + (size_t)bc * HW + (yd * 8) * WW + xd * 8;
    float s = 0.f;
    #pragma unroll
    for (int i = 0; i < 8; i++) {
        float4 a = *reinterpret_cast<const float4*>(xp + i * WW);
        float4 bq = *reinterpret_cast<const float4*>(xp + i * WW + 4);
        s += (a.x + a.y + a.z + a.w) + (bq.x + bq.y + bq.z + bq.w);
    }
    g_xdown[idx] = s * (1.f / 64.f);
}

// ------------------------- 3x3 depthwise (32x32) ----------------------------
__global__ __launch_bounds__(256) void dw3x3_small_kernel(const float* __restrict__ w)
{
    const int zc = blockIdx.x;
    const int c = zc % 576;
    __shared__ float xs[34][34];
    __shared__ float w3[9];
    const int tid = threadIdx.x;
    const float* ip = g_qkv + (size_t)zc * PD;
    if (tid < 9) w3[tid] = w[c * 9 + tid];
    for (int i = tid; i < 34 * 34; i += 256) {
        int r = i / 34, cc = i % 34;
        int gy = r - 1, gx = cc - 1;
        xs[r][cc] = (gy >= 0 && gy < HD && gx >= 0 && gx < WD) ? ip[gy * WD + gx] : 0.f;
    }
    __syncthreads();
    const int tx = tid & 31, ty = tid >> 5;
    float* op = g_qkvdw + (size_t)zc * PD;
    #pragma unroll
    for (int rr = 0; rr < 4; rr++) {
        int oy = ty + rr * 8;
        float s = 0.f;
        #pragma unroll
        for (int ky = 0; ky < 3; ky++)
            #pragma unroll
            for (int kx = 0; kx < 3; kx++)
                s = fmaf(xs[oy + ky][tx + kx], w3[ky * 3 + kx], s);
        op[oy * WD + tx] = s;
    }
}

// --------------- attention Gram + softmax (coalesced, chunked) --------------
__global__ void attn_kernel2(const float* __restrict__ temp)
{
    const int bh = blockIdx.x;
    const int b = bh / HEADS, h = bh % HEADS;
    const float* q = g_qkvdw + ((size_t)b * 576 + h * CH) * PD;
    const float* kk = g_qkvdw + ((size_t)b * 576 + DIMC + h * CH) * PD;

    __shared__ float qs[CH][65], ks[CH][65];
    __shared__ float qn[CH], kn[CH], sm[CH][CH];
    const int tid = threadIdx.x;            // 576
    const int c = tid / CH, d = tid % CH;

    float acc = 0.f, accq = 0.f, acck = 0.f;
    for (int chn = 0; chn < 16; chn++) {
        #pragma unroll
        for (int i = 0; i < 3; i++) {
            int e = tid + i * 576;
            if (e < CH * 64) {
                int r = e >> 6, cc = e & 63;
                qs[r][cc] = q[(size_t)r * PD + chn * 64 + cc];
                ks[r][cc] = kk[(size_t)r * PD + chn * 64 + cc];
            }
        }
        __syncthreads();
        #pragma unroll 8
        for (int i = 0; i < 64; i++)
            acc = fmaf(qs[c][i], ks[d][i], acc);
        if (c == d) {
            #pragma unroll 8
            for (int i = 0; i < 64; i++) {
                accq = fmaf(qs[c][i], qs[c][i], accq);
                acck = fmaf(ks[c][i], ks[c][i], acck);
            }
        }
        __syncthreads();
    }
    if (c == d) {
        qn[c] = fmaxf(sqrtf(accq), 1e-12f);
        kn[c] = fmaxf(sqrtf(acck), 1e-12f);
    }
    __syncthreads();
    sm[c][d] = acc / (qn[c] * kn[d]) * temp[h];
    __syncthreads();
    if (tid < CH) {
        float m = -1e30f;
        for (int j = 0; j < CH; j++) m = fmaxf(m, sm[tid][j]);
        float e[CH]; float ssum = 0.f;
        for (int j = 0; j < CH; j++) { e[j] = expf(sm[tid][j] - m); ssum += e[j]; }
        float inv = 1.f / ssum;
        for (int j = 0; j < CH; j++)
            g_attn[((size_t)bh * CH + tid) * CH + j] = e[j] * inv;
    }
}

// ------------------------------ v gate (coalesced) ---------------------------
__global__ void vgate_kernel2(const float* __restrict__ w2, const float* __restrict__ w3)
{
    const int b = blockIdx.x;
    const float* v = g_qkvdw + ((size_t)b * 576 + 2 * DIMC) * PD;
    __shared__ float vmax[DIMC], vavg[DIMC];
    const int tid = threadIdx.x;   // 256
    const int wid = tid >> 5, lane = tid & 31;
    for (int c = wid; c < DIMC; c += 8) {
        const float* p = v + (size_t)c * PD;
        float m = -1e30f, s = 0.f;
        for (int i = lane; i < PD; i += 32) { float vv = p[i]; m = fmaxf(m, vv); s += vv; }
        #pragma unroll
        for (int off = 16; off; off >>= 1) {
            m = fmaxf(m, __shfl_xor_sync(0xFFFFFFFF, m, off));
            s += __shfl_xor_sync(0xFFFFFFFF, s, off);
        }
        if (lane == 0) { vmax[c] = m; vavg[c] = s * (1.f / (float)PD); }
    }
    __syncthreads();
    if (tid < DIMC) {
        float g = 0.f;
        for (int c = 0; c < DIMC; c++)
            g = fmaf(w2[tid * DIMC + c], vmax[c], fmaf(w3[tid * DIMC + c], vavg[c], g));
        g_gate[b * DIMC + tid] = g;
    }
}

// -------- fused dw3x3(conv4b) * gate + attention apply -> cat[192:384) -------
__global__ __launch_bounds__(256) void dwattn_kernel(const float* __restrict__ w4b)
{
    const int z = blockIdx.z;
    const int b = z >> 3, h = z & 7;
    const int x0 = blockIdx.x * 32, y0 = blockIdx.y * 8;
    const int tid = threadIdx.x;

    __shared__ float xs[CH][10][36];
    __shared__ float a2[CH][CH];
    __shared__ float w3s[CH][9];

    const float* tb = g_t4 + ((size_t)b * DIMC + h * CH) * HW;
    for (int i = tid; i < CH * 10 * 34; i += 256) {
        int d = i / 340, rem = i % 340;
        int r = rem / 34, cx = rem % 34;
        int gy = y0 - 1 + r, gx = x0 - 1 + cx;
        float v = 0.f;
        if (gy >= 0 && gy < HH && gx >= 0 && gx < WW)
            v = tb[(size_t)d * HW + gy * WW + gx];
        xs[d][r][cx] = v;
    }
    if (tid < CH * 9) {
        int d = tid / 9;
        w3s[d][tid % 9] = w4b[(h * CH + d) * 9 + tid % 9];
    }
    // FIX (R5): CH*CH = 576 > blockDim (256) — must loop, not mask.
    for (int i = tid; i < CH * CH; i += 256) {
        int c = i / CH, d = i % CH;
        a2[c][d] = g_attn[((size_t)(b * HEADS + h) * CH + c) * CH + d] *
                   g_gate[b * DIMC + h * CH + d];
    }
    __syncthreads();

    const int tx = tid & 31, ty = tid >> 5;
    float dw[CH];
    #pragma unroll
    for (int d = 0; d < CH; d++) {
        float s = 0.f;
        #pragma unroll
        for (int ky = 0; ky < 3; ky++)
            #pragma unroll
            for (int kx = 0; kx < 3; kx++)
                s = fmaf(xs[d][ty + ky][tx + kx], w3s[d][ky * 3 + kx], s);
        dw[d] = s;
    }
    float* ob = g_cat + ((size_t)b * 384 + DIMC + h * CH) * HW + (y0 + ty) * WW + x0 + tx;
    #pragma unroll
    for (int c = 0; c < CH; c++) {
        float s = 0.f;
        #pragma unroll
        for (int d = 0; d < CH; d++) s = fmaf(a2[c][d], dw[d], s);
        ob[(size_t)c * HW] = s;
    }
}

// ------------------------------- launch -------------------------------------
extern "C" void kernel_launch(void* const* d_in, const int* in_sizes, int n_in,
                              void* d_out, int out_size)
{
    const float* x        = (const float*)d_in[0];
    const float* w_dww    = (const float*)d_in[1];
    const float* b_dww    = (const float*)d_in[2];
    const float* w_dwh    = (const float*)d_in[3];
    const float* b_dwh    = (const float*)d_in[4];
    const float* w_dwhw   = (const float*)d_in[5];
    const float* b_dwhw   = (const float*)d_in[6];
    const float* w_conv1  = (const float*)d_in[7];
    const float* w_qkv    = (const float*)d_in[8];
    const float* w_qkvdw  = (const float*)d_in[9];
    const float* w_conv2  = (const float*)d_in[10];
    const float* w_conv3  = (const float*)d_in[11];
    const float* w_conv4a = (const float*)d_in[12];
    const float* w_conv4b = (const float*)d_in[13];
    const float* w_proj   = (const float*)d_in[14];
    const float* temp     = (const float*)d_in[15];
    float* out = (float*)d_out;

    float *p_hcatdw, *p_cat, *p_t4, *p_xdown, *p_qkv;
    __nv_bfloat16 *p_w1h, *p_w1l, *p_w4h, *p_w4l, *p_wph, *p_wpl;
    cudaGetSymbolAddress((void**)&p_hcatdw, g_hcatdw);
    cudaGetSymbolAddress((void**)&p_cat,    g_cat);
    cudaGetSymbolAddress((void**)&p_t4,     g_t4);
    cudaGetSymbolAddress((void**)&p_xdown,  g_xdown);
    cudaGetSymbolAddress((void**)&p_qkv,    g_qkv);
    cudaGetSymbolAddress((void**)&p_w1h,    g_w1h);
    cudaGetSymbolAddress((void**)&p_w1l,    g_w1l);
    cudaGetSymbolAddress((void**)&p_w4h,    g_w4h);
    cudaGetSymbolAddress((void**)&p_w4l,    g_w4l);
    cudaGetSymbolAddress((void**)&p_wph,    g_wph);
    cudaGetSymbolAddress((void**)&p_wpl,    g_wpl);

    cudaFuncSetAttribute(fgemm_kernel,
                         cudaFuncAttributeMaxDynamicSharedMemorySize, SMEMT);

    // #1-3 weight splits
    convw_kernel<<<(192 * 384 + 255) / 256, 256>>>(w_conv1, p_w1h, p_w1l, 192 * 384);
    convw_kernel<<<(192 * 192 + 255) / 256, 256>>>(w_conv4a, p_w4h, p_w4l, 192 * 192);
    convw_kernel<<<(192 * 384 + 255) / 256, 256>>>(w_proj, p_wph, p_wpl, 192 * 384);

    // #4 high-branch depthwise stack
    highpre_kernel<<<dim3(WW / 32, HH / 32, BATCH * 384), 256>>>(
        x, w_dww, b_dww, w_dwh, b_dwh, w_dwhw, b_dwhw);

    // #5 pool
    pool_kernel<<<(BATCH * DIMC * PD + 255) / 256, 256>>>(x);

    // #6 conv1: cat[:,0:192) = W1 @ hcatdw   (profiled launch)
    fgemm_kernel<<<dim3(HW / 128, 1, BATCH), 256, SMEMT>>>(
        p_hcatdw, 384, p_w1h, p_w1l, p_cat, 384, 0);

    // low branch
    gemm_kernel<<<dim3(PD / BN, 576 / BM, BATCH), 256>>>(
        w_qkv, p_xdown, p_qkv, DIMC, PD, (size_t)DIMC * PD, (size_t)576 * PD);
    dw3x3_small_kernel<<<BATCH * 576, 256>>>(w_qkvdw);
    attn_kernel2<<<BATCH * HEADS, 576>>>(temp);
    vgate_kernel2<<<BATCH, 256>>>(w_conv2, w_conv3);

    // conv4a: t4 = W4a @ x
    fgemm_kernel<<<dim3(HW / 128, 1, BATCH), 256, SMEMT>>>(
        x, DIMC, p_w4h, p_w4l, p_t4, DIMC, 0);

    // fused dw(conv4b)*gate + attn apply -> cat[:,192:384)
    dwattn_kernel<<<dim3(WW / 32, HH / 8, BATCH * HEADS), 256>>>(w_conv4b);

    // proj: out = Wp @ cat
    fgemm_kernel<<<dim3(HW / 128, 1, BATCH), 256, SMEMT>>>(
        p_cat, 384, p_wph, p_wpl, out, DIMC, 0);
}